// round 4
// baseline (speedup 1.0000x reference)
#include <cuda_runtime.h>
#include <cuda_bf16.h>

// QuantumLSTMCell — analytic collapse:
// <Z_0> = cos(theta[0]) * cos(a[:,0])  (Z_0 commutes with the CNOT chain;
// pre-CNOT state is a product state). Only row 0 of each W and element 0 of
// each bias/theta matter.
//
// Two-kernel split:
//   K1 (gates): warp-per-row GEMV over comb=[x|hx] (1280), all-float4 loads.
//               Writes packed {f, i*g, o, 0} per row.
//   K2 (elementwise): barrier-free streaming LSTM update.
//
// B=16384, D=256, H=1024.

#define B_ROWS 16384
#define D_DIM  256
#define H_DIM  1024

// Packed per-row gate values: {f, i*g, o, pad}
__device__ float4 g_gates[B_ROWS];

__device__ __forceinline__ float sigmoidf_(float v) {
    return 1.0f / (1.0f + expf(-v));
}

// ---------------------------------------------------------------------------
// Kernel 1: gates. 8 warps/block, one warp per batch row. Grid = B/8 = 2048.
// ---------------------------------------------------------------------------
__global__ __launch_bounds__(256)
void qlstm_gates_kernel(
    const float* __restrict__ x,   // [B, 256]
    const float* __restrict__ hx,  // [B, 1024]
    const float* __restrict__ Wf, const float* __restrict__ bf,
    const float* __restrict__ Wi, const float* __restrict__ bi,
    const float* __restrict__ Wg, const float* __restrict__ bg,
    const float* __restrict__ Wo, const float* __restrict__ bo,
    const float* __restrict__ thf, const float* __restrict__ thi,
    const float* __restrict__ thg, const float* __restrict__ tho)
{
    const int lane = threadIdx.x & 31;
    const int warp = threadIdx.x >> 5;
    const int row  = blockIdx.x * 8 + warp;

    const float4* x4  = (const float4*)(x  + (size_t)row * D_DIM);  // 64 float4
    const float4* h4  = (const float4*)(hx + (size_t)row * H_DIM);  // 256 float4
    const float4* wf4 = (const float4*)Wf;   // row 0: first 320 float4
    const float4* wi4 = (const float4*)Wi;
    const float4* wg4 = (const float4*)Wg;
    const float4* wo4 = (const float4*)Wo;

    float sf = 0.f, si = 0.f, sg = 0.f, so = 0.f;

    #pragma unroll
    for (int k = 0; k < 2; k++) {           // x part: 64 float4
        int j = lane + 32 * k;
        float4 v = x4[j];
        float4 a = __ldg(&wf4[j]);
        float4 b = __ldg(&wi4[j]);
        float4 c = __ldg(&wg4[j]);
        float4 d = __ldg(&wo4[j]);
        sf += v.x*a.x + v.y*a.y + v.z*a.z + v.w*a.w;
        si += v.x*b.x + v.y*b.y + v.z*b.z + v.w*b.w;
        sg += v.x*c.x + v.y*c.y + v.z*c.z + v.w*c.w;
        so += v.x*d.x + v.y*d.y + v.z*d.z + v.w*d.w;
    }
    #pragma unroll
    for (int k = 0; k < 8; k++) {           // hx part: 256 float4, offset 64
        int j = lane + 32 * k;
        float4 v = h4[j];
        float4 a = __ldg(&wf4[64 + j]);
        float4 b = __ldg(&wi4[64 + j]);
        float4 c = __ldg(&wg4[64 + j]);
        float4 d = __ldg(&wo4[64 + j]);
        sf += v.x*a.x + v.y*a.y + v.z*a.z + v.w*a.w;
        si += v.x*b.x + v.y*b.y + v.z*b.z + v.w*b.w;
        sg += v.x*c.x + v.y*c.y + v.z*c.z + v.w*c.w;
        so += v.x*d.x + v.y*d.y + v.z*d.z + v.w*d.w;
    }

    // warp reduction (4 values)
    #pragma unroll
    for (int off = 16; off > 0; off >>= 1) {
        sf += __shfl_xor_sync(0xffffffffu, sf, off);
        si += __shfl_xor_sync(0xffffffffu, si, off);
        sg += __shfl_xor_sync(0xffffffffu, sg, off);
        so += __shfl_xor_sync(0xffffffffu, so, off);
    }

    if (lane == 0) {
        float af = sf + __ldg(&bf[0]);
        float ai = si + __ldg(&bi[0]);
        float ag = sg + __ldg(&bg[0]);
        float ao = so + __ldg(&bo[0]);
        float f  = sigmoidf_(cosf(__ldg(&thf[0])) * cosf(af));
        float i  = sigmoidf_(cosf(__ldg(&thi[0])) * cosf(ai));
        float g  = tanhf   (cosf(__ldg(&thg[0])) * cosf(ag));
        float o  = sigmoidf_(cosf(__ldg(&tho[0])) * cosf(ao));
        g_gates[row] = make_float4(f, i * g, o, 0.f);
    }
}

// ---------------------------------------------------------------------------
// Kernel 2: elementwise LSTM update. Pure streaming, no barriers.
// 2 float4 per thread. Total float4 = B*H/4 = 4,194,304 -> grid 8192 x 256.
// ---------------------------------------------------------------------------
__global__ __launch_bounds__(256)
void qlstm_ew_kernel(
    const float* __restrict__ cx,
    float* __restrict__ out_h,
    float* __restrict__ out_c)
{
    const float4* c4  = (const float4*)cx;
    float4*       h4o = (float4*)out_h;
    float4*       c4o = (float4*)out_c;

    const int base = blockIdx.x * 512 + threadIdx.x;

    #pragma unroll
    for (int r = 0; r < 2; r++) {
        const int idx = base + r * 256;       // float4 index, < 4,194,304
        const int row = idx >> 8;             // 256 float4 per row
        const float4 g = g_gates[row];        // broadcast within block (L1 hit)
        const float fg = g.x, igg = g.y, og = g.z;

        float4 cv = c4[idx];
        float4 nc, nh;
        nc.x = fg * cv.x + igg;
        nc.y = fg * cv.y + igg;
        nc.z = fg * cv.z + igg;
        nc.w = fg * cv.w + igg;
        nh.x = og * tanhf(nc.x);
        nh.y = og * tanhf(nc.y);
        nh.z = og * tanhf(nc.z);
        nh.w = og * tanhf(nc.w);
        c4o[idx] = nc;
        h4o[idx] = nh;
    }
}

extern "C" void kernel_launch(void* const* d_in, const int* in_sizes, int n_in,
                              void* d_out, int out_size) {
    // metadata order: x, hx, cx, Wf, bf, Wi, bi, Wg, bg, Wo, bo,
    //                 theta_f, theta_i, theta_g, theta_o
    const float* x   = (const float*)d_in[0];
    const float* hx  = (const float*)d_in[1];
    const float* cx  = (const float*)d_in[2];
    const float* Wf  = (const float*)d_in[3];
    const float* bf  = (const float*)d_in[4];
    const float* Wi  = (const float*)d_in[5];
    const float* bi  = (const float*)d_in[6];
    const float* Wg  = (const float*)d_in[7];
    const float* bg  = (const float*)d_in[8];
    const float* Wo  = (const float*)d_in[9];
    const float* bo  = (const float*)d_in[10];
    const float* thf = (const float*)d_in[11];
    const float* thi = (const float*)d_in[12];
    const float* thg = (const float*)d_in[13];
    const float* tho = (const float*)d_in[14];

    float* out   = (float*)d_out;
    float* out_h = out;                                   // new_h first
    float* out_c = out + (size_t)B_ROWS * H_DIM;          // new_c second

    qlstm_gates_kernel<<<B_ROWS / 8, 256>>>(x, hx,
                                            Wf, bf, Wi, bi, Wg, bg, Wo, bo,
                                            thf, thi, thg, tho);
    qlstm_ew_kernel<<<8192, 256>>>(cx, out_h, out_c);
}